// round 11
// baseline (speedup 1.0000x reference)
#include <cuda_runtime.h>
#include <cuda_fp16.h>
#include <math.h>

#define NN 100000
#define FD 500
#define NC 64
#define KH 10
#define EMAX 3200000
#define NB_SCAN ((NN + 1023) / 1024)
#define SLICE ((size_t)(NN + 1) * 32)   // half2 per y slice (+1 sentinel row)

// ---- scratch (no allocations allowed) ----
__device__ __half2 g_yH[(size_t)(KH + 1) * SLICE]; // y_0..y_K history (fp16)
__device__ float g_dinv[NN];
__device__ float g_sdeg[NN];
__device__ int   g_cnt[NN];
__device__ int   g_cursor[NN];
__device__ int   g_off[NN + 1];
__device__ int   g_bsum[NB_SCAN];
__device__ int   g_src[EMAX];

// ---------------- in-degree count ----------------
__global__ void cnt_zero_kernel() {
    int i = blockIdx.x * blockDim.x + threadIdx.x;
    if (i < NN) g_cnt[i] = 0;
}

__global__ void cnt_acc_kernel(const int* __restrict__ col, int E) {
    int e = blockIdx.x * blockDim.x + threadIdx.x;
    if (e < E) atomicAdd(&g_cnt[col[e]], 1);
}

// dinv/sdeg from counts (runs before mlp so mlp sits at ncu capture slot 3)
__global__ void dinv_kernel() {
    int i = blockIdx.x * blockDim.x + threadIdx.x;
    if (i < NN) {
        float deg = (float)(g_cnt[i] + 1);   // + self loop
        g_dinv[i] = rsqrtf(deg);
        g_sdeg[i] = sqrtf(deg);
        g_cursor[i] = 0;
    }
}

// ---------------- scan ----------------
__global__ __launch_bounds__(1024) void scan1_kernel() {
    __shared__ int sh[1024];
    int i = blockIdx.x * 1024 + threadIdx.x;
    int v = (i < NN) ? g_cnt[i] : 0;
    sh[threadIdx.x] = v;
    __syncthreads();
#pragma unroll
    for (int off = 1; off < 1024; off <<= 1) {
        int t = 0;
        if (threadIdx.x >= off) t = sh[threadIdx.x - off];
        __syncthreads();
        if (threadIdx.x >= off) sh[threadIdx.x] += t;
        __syncthreads();
    }
    if (i < NN) g_off[i] = sh[threadIdx.x] - v;
    if (threadIdx.x == 1023) g_bsum[blockIdx.x] = sh[1023];
}

// warp-scan over the ~98 block sums
__global__ void scan2_kernel() {
    int lane = threadIdx.x;
    int run = 0;
    for (int b0 = 0; b0 < NB_SCAN; b0 += 32) {
        int idx = b0 + lane;
        int orig = (idx < NB_SCAN) ? g_bsum[idx] : 0;
        int v = orig;
#pragma unroll
        for (int off = 1; off < 32; off <<= 1) {
            int t = __shfl_up_sync(0xFFFFFFFFu, v, off);
            if (lane >= off) v += t;
        }
        if (idx < NB_SCAN) g_bsum[idx] = run + v - orig;  // exclusive
        run += __shfl_sync(0xFFFFFFFFu, v, 31);
    }
    if (lane == 0) g_off[NN] = run;
}

__global__ __launch_bounds__(1024) void scan3_kernel() {
    int i = blockIdx.x * 1024 + threadIdx.x;
    if (i < NN) g_off[i] += g_bsum[blockIdx.x];
}

// ---------------- CSR fill (+ sentinel rows in history slices) ----------------
__global__ void fill_kernel(const int* __restrict__ row, const int* __restrict__ col, int E) {
    int e = blockIdx.x * blockDim.x + threadIdx.x;
    if (e < (KH + 1) * 32) {   // zero the sentinel row (index NN) in every slice
        int k = e >> 5, l = e & 31;
        g_yH[(size_t)k * SLICE + (size_t)NN * 32 + l] = __float2half2_rn(0.0f);
    }
    if (e < E) {
        int c = col[e];
        int p = atomicAdd(&g_cursor[c], 1);
        g_src[g_off[c] + p] = row[e];
    }
}

// ---------------- tensor-core MLP: 128 threads / 64 rows per block ----------------
// y0 = dinv * (relu(x@W1+b1)@W2 + b2) -> g_yH slice 0 (fp16)
__global__ __launch_bounds__(128) void mlp_kernel(
    const float* __restrict__ x,
    const float* __restrict__ W1, const float* __restrict__ b1,
    const float* __restrict__ W2, const float* __restrict__ b2)
{
    __shared__ __half Ax[64][72];    // x tile (then h1 tile), padded pitch
    __shared__ __half Wt[64][72];    // W chunk transposed: Wt[n][k]

    const int t = threadIdx.x;
    const int lane = t & 31;
    const int w = t >> 5;            // 0..3
    const int row0 = blockIdx.x * 64;
    const int wr0 = w * 16;

    const int frow = lane >> 2;       // 0..7
    const int fkp  = (lane & 3) * 2;  // 0,2,4,6

    float c[8][4];
#pragma unroll
    for (int nt = 0; nt < 8; nt++)
#pragma unroll
        for (int i = 0; i < 4; i++) c[nt][i] = 0.0f;

    for (int s = 0; s < 8; s++) {
        const int k0 = s * 64;
        __syncthreads();
        // ---- stage x[rows, k0:k0+64] -> Ax (fp16), zero-pad beyond FD ----
        {
            int c4 = lane & 15;
            int hh = lane >> 4;
#pragma unroll
            for (int rr = 0; rr < 8; rr++) {
                int rl = rr * 2 + hh;
                int gr = row0 + wr0 + rl;
                int gk = k0 + c4 * 4;
                float4 xv = make_float4(0.f, 0.f, 0.f, 0.f);
                if (gr < NN && gk < FD)
                    xv = *reinterpret_cast<const float4*>(&x[(size_t)gr * FD + gk]);
                __half2 p0 = __floats2half2_rn(xv.x, xv.y);
                __half2 p1 = __floats2half2_rn(xv.z, xv.w);
                uint2 pk;
                pk.x = *reinterpret_cast<unsigned*>(&p0);
                pk.y = *reinterpret_cast<unsigned*>(&p1);
                *reinterpret_cast<uint2*>(&Ax[wr0 + rl][c4 * 4]) = pk;
            }
        }
        // ---- stage W1[k0:k0+64, :] transposed -> Wt[n][k] ----
        {
            int n = t & 63;
            int kb = t >> 6;           // 0..1
#pragma unroll
            for (int i = 0; i < 32; i++) {
                int kk = kb + i * 2;
                int gk = k0 + kk;
                Wt[n][kk] = (gk < FD) ? __float2half(W1[gk * 64 + n]) : __half(0.0f);
            }
        }
        __syncthreads();
#pragma unroll
        for (int ks = 0; ks < 4; ks++) {
            const int kb = ks * 16;
            unsigned a0 = *reinterpret_cast<const unsigned*>(&Ax[wr0 + frow][kb + fkp]);
            unsigned a1 = *reinterpret_cast<const unsigned*>(&Ax[wr0 + frow + 8][kb + fkp]);
            unsigned a2 = *reinterpret_cast<const unsigned*>(&Ax[wr0 + frow][kb + fkp + 8]);
            unsigned a3 = *reinterpret_cast<const unsigned*>(&Ax[wr0 + frow + 8][kb + fkp + 8]);
#pragma unroll
            for (int nt = 0; nt < 8; nt++) {
                int n = nt * 8 + frow;
                unsigned b0 = *reinterpret_cast<const unsigned*>(&Wt[n][kb + fkp]);
                unsigned b1r = *reinterpret_cast<const unsigned*>(&Wt[n][kb + fkp + 8]);
                asm volatile(
                    "mma.sync.aligned.m16n8k16.row.col.f32.f16.f16.f32 "
                    "{%0,%1,%2,%3}, {%4,%5,%6,%7}, {%8,%9}, {%0,%1,%2,%3};"
                    : "+f"(c[nt][0]), "+f"(c[nt][1]), "+f"(c[nt][2]), "+f"(c[nt][3])
                    : "r"(a0), "r"(a1), "r"(a2), "r"(a3), "r"(b0), "r"(b1r));
            }
        }
    }

    // ---- epilogue 1: h1 = relu(c + b1) -> Ax ----
#pragma unroll
    for (int nt = 0; nt < 8; nt++) {
        int n0 = nt * 8 + fkp;
        float2 bb = __ldg(reinterpret_cast<const float2*>(&b1[n0]));
        float h00 = fmaxf(c[nt][0] + bb.x, 0.f);
        float h01 = fmaxf(c[nt][1] + bb.y, 0.f);
        float h10 = fmaxf(c[nt][2] + bb.x, 0.f);
        float h11 = fmaxf(c[nt][3] + bb.y, 0.f);
        __half2 p0 = __floats2half2_rn(h00, h01);
        __half2 p1 = __floats2half2_rn(h10, h11);
        *reinterpret_cast<unsigned*>(&Ax[wr0 + frow][n0]) = *reinterpret_cast<unsigned*>(&p0);
        *reinterpret_cast<unsigned*>(&Ax[wr0 + frow + 8][n0]) = *reinterpret_cast<unsigned*>(&p1);
    }
    __syncthreads();
    // ---- stage W2 transposed -> Wt ----
    {
        int n = t & 63;
        int kb = t >> 6;
#pragma unroll
        for (int i = 0; i < 32; i++) {
            int kk = kb + i * 2;
            Wt[n][kk] = __float2half(W2[kk * 64 + n]);
        }
    }
#pragma unroll
    for (int nt = 0; nt < 8; nt++)
#pragma unroll
        for (int i = 0; i < 4; i++) c[nt][i] = 0.0f;
    __syncthreads();

    // ---- GEMM2: h1 @ W2 ----
#pragma unroll
    for (int ks = 0; ks < 4; ks++) {
        const int kb = ks * 16;
        unsigned a0 = *reinterpret_cast<const unsigned*>(&Ax[wr0 + frow][kb + fkp]);
        unsigned a1 = *reinterpret_cast<const unsigned*>(&Ax[wr0 + frow + 8][kb + fkp]);
        unsigned a2 = *reinterpret_cast<const unsigned*>(&Ax[wr0 + frow][kb + fkp + 8]);
        unsigned a3 = *reinterpret_cast<const unsigned*>(&Ax[wr0 + frow + 8][kb + fkp + 8]);
#pragma unroll
        for (int nt = 0; nt < 8; nt++) {
            int n = nt * 8 + frow;
            unsigned b0 = *reinterpret_cast<const unsigned*>(&Wt[n][kb + fkp]);
            unsigned b1r = *reinterpret_cast<const unsigned*>(&Wt[n][kb + fkp + 8]);
            asm volatile(
                "mma.sync.aligned.m16n8k16.row.col.f32.f16.f16.f32 "
                "{%0,%1,%2,%3}, {%4,%5,%6,%7}, {%8,%9}, {%0,%1,%2,%3};"
                : "+f"(c[nt][0]), "+f"(c[nt][1]), "+f"(c[nt][2]), "+f"(c[nt][3])
                : "r"(a0), "r"(a1), "r"(a2), "r"(a3), "r"(b0), "r"(b1r));
        }
    }

    // ---- epilogue 2: y0 = dinv*(c+b2) -> g_yH slice 0 ----
    int gr0 = row0 + wr0 + frow;
    int gr1 = gr0 + 8;
    float d0 = (gr0 < NN) ? g_dinv[gr0] : 0.f;
    float d1 = (gr1 < NN) ? g_dinv[gr1] : 0.f;
#pragma unroll
    for (int nt = 0; nt < 8; nt++) {
        int n0 = nt * 8 + fkp;
        float2 bb = __ldg(reinterpret_cast<const float2*>(&b2[n0]));
        float y00 = d0 * (c[nt][0] + bb.x);
        float y01 = d0 * (c[nt][1] + bb.y);
        float y10 = d1 * (c[nt][2] + bb.x);
        float y11 = d1 * (c[nt][3] + bb.y);
        if (gr0 < NN) g_yH[(size_t)gr0 * 32 + n0 / 2] = __floats2half2_rn(y00, y01);
        if (gr1 < NN) g_yH[(size_t)gr1 * 32 + n0 / 2] = __floats2half2_rn(y10, y11);
    }
}

// ---------------- pull propagation: warp per node ----------------
// full 32-edge blocks: guard-free, 4 chunks x (2 HADD2 chains of 4); tail guarded per 8.
__global__ __launch_bounds__(256) void propagate_kernel(int k) {
    const __half2* __restrict__ y = g_yH + (size_t)k * SLICE;
    __half2* __restrict__ yn = g_yH + (size_t)(k + 1) * SLICE;
    int node = (blockIdx.x * blockDim.x + threadIdx.x) >> 5;
    int lane = threadIdx.x & 31;
    if (node >= NN) return;

    float d = g_dinv[node];
    float2 self = __half22float2(__ldg(&y[(size_t)node * 32 + lane]));
    float ax = self.x, ay = self.y;   // self-loop term

    int beg = g_off[node];
    int end = g_off[node + 1];
    int nfull = (end - beg) & ~31;
    int i = beg;

    // ---- full 32-edge blocks: no guards inside ----
    for (; i < beg + nfull; i += 32) {
        int s = __ldg(&g_src[i + lane]);
#pragma unroll
        for (int t = 0; t < 4; t++) {
            __half2 h0 = __float2half2_rn(0.0f);
            __half2 h1 = __float2half2_rn(0.0f);
#pragma unroll
            for (int j = 0; j < 4; j++) {
                int sj0 = __shfl_sync(0xFFFFFFFFu, s, t * 8 + j);
                int sj1 = __shfl_sync(0xFFFFFFFFu, s, t * 8 + 4 + j);
                h0 = __hadd2(h0, __ldg(&y[(size_t)sj0 * 32 + lane]));
                h1 = __hadd2(h1, __ldg(&y[(size_t)sj1 * 32 + lane]));
            }
            float2 f = __half22float2(__hadd2(h0, h1));
            ax += f.x;
            ay += f.y;
        }
    }

    // ---- tail (< 32 edges): guarded per 8-chunk ----
    if (i < end) {
        int s = (i + lane < end) ? __ldg(&g_src[i + lane]) : NN;  // sentinel zero row
#pragma unroll
        for (int t = 0; t < 4; t++) {
            if (i + t * 8 < end) {
                __half2 h0 = __float2half2_rn(0.0f);
                __half2 h1 = __float2half2_rn(0.0f);
#pragma unroll
                for (int j = 0; j < 4; j++) {
                    int sj0 = __shfl_sync(0xFFFFFFFFu, s, t * 8 + j);
                    int sj1 = __shfl_sync(0xFFFFFFFFu, s, t * 8 + 4 + j);
                    h0 = __hadd2(h0, __ldg(&y[(size_t)sj0 * 32 + lane]));
                    h1 = __hadd2(h1, __ldg(&y[(size_t)sj1 * 32 + lane]));
                }
                float2 f = __half22float2(__hadd2(h0, h1));
                ax += f.x;
                ay += f.y;
            }
        }
    }

    float d2 = d * d;
    yn[(size_t)node * 32 + lane] = __floats2half2_rn(d2 * ax, d2 * ay);
}

// ---------------- final: hidden = sdeg * sum_k temp[k]*y_k ; log_softmax ----------------
__global__ void final_kernel(const float* __restrict__ temp, float* __restrict__ out) {
    int node = (blockIdx.x * blockDim.x + threadIdx.x) >> 5;
    int lane = threadIdx.x & 31;
    if (node >= NN) return;
    float sd = g_sdeg[node];
    float ax = 0.f, ay = 0.f;
#pragma unroll
    for (int k = 0; k <= KH; k++) {
        float tk = __ldg(&temp[k]);
        float2 v = __half22float2(__ldg(&g_yH[(size_t)k * SLICE + (size_t)node * 32 + lane]));
        ax += tk * v.x;
        ay += tk * v.y;
    }
    float a = ax * sd, b = ay * sd;   // features 2*lane, 2*lane+1
    float mx = fmaxf(a, b);
#pragma unroll
    for (int off = 16; off > 0; off >>= 1)
        mx = fmaxf(mx, __shfl_xor_sync(0xFFFFFFFFu, mx, off));
    float s = expf(a - mx) + expf(b - mx);
#pragma unroll
    for (int off = 16; off > 0; off >>= 1)
        s += __shfl_xor_sync(0xFFFFFFFFu, s, off);
    float l = mx + logf(s);
    *reinterpret_cast<float2*>(&out[(size_t)node * NC + lane * 2]) = make_float2(a - l, b - l);
}

// ---------------- launch ----------------
extern "C" void kernel_launch(void* const* d_in, const int* in_sizes, int n_in,
                              void* d_out, int out_size)
{
    const float* x    = (const float*)d_in[0];
    const int*   ei   = (const int*)d_in[1];
    const float* W1   = (const float*)d_in[2];
    const float* b1   = (const float*)d_in[3];
    const float* W2   = (const float*)d_in[4];
    const float* b2   = (const float*)d_in[5];
    const float* temp = (const float*)d_in[6];
    float* out = (float*)d_out;

    const int E = in_sizes[1] / 2;
    const int* row = ei;       // source
    const int* col = ei + E;   // target

    // launches 0..2, then MLP at index 3 (ncu capture slot)
    cnt_zero_kernel<<<(NN + 255) / 256, 256>>>();
    cnt_acc_kernel<<<(E + 255) / 256, 256>>>(col, E);
    dinv_kernel<<<(NN + 255) / 256, 256>>>();
    mlp_kernel<<<(NN + 63) / 64, 128>>>(x, W1, b1, W2, b2);

    // CSR build
    scan1_kernel<<<NB_SCAN, 1024>>>();
    scan2_kernel<<<1, 32>>>();
    scan3_kernel<<<NB_SCAN, 1024>>>();
    fill_kernel<<<(E + 255) / 256, 256>>>(row, col, E);

    // pull propagation: 1 warp per node, y_k history in g_yH
    int pblocks = (NN * 32 + 255) / 256;
    for (int k = 0; k < KH; k++) {
        propagate_kernel<<<pblocks, 256>>>(k);
    }

    final_kernel<<<(NN * 32 + 255) / 256, 256>>>(temp, out);
}

// round 12
// speedup vs baseline: 1.0787x; 1.0787x over previous
#include <cuda_runtime.h>
#include <cuda_fp16.h>
#include <math.h>

#define NN 100000
#define FD 500
#define NC 64
#define KH 10
#define EMAX 3200000
#define NB_SCAN ((NN + 1023) / 1024)
#define SLICE ((size_t)(NN + 1) * 32)   // half2 per y slice (+1 sentinel row)

// ---- scratch (no allocations allowed) ----
__device__ __half2 g_yH[(size_t)(KH + 1) * SLICE]; // y_0..y_K history (fp16)
__device__ float g_dinv[NN];
__device__ float g_sdeg[NN];
__device__ int   g_cnt[NN];
__device__ int   g_cursor[NN];
__device__ int   g_off[NN + 1];
__device__ int   g_bsum[NB_SCAN];
__device__ int   g_src[EMAX];

// ---------------- in-degree count ----------------
__global__ void cnt_zero_kernel() {
    int i = blockIdx.x * blockDim.x + threadIdx.x;
    if (i < NN) g_cnt[i] = 0;
}

__global__ void cnt_acc_kernel(const int* __restrict__ col, int E) {
    int e = blockIdx.x * blockDim.x + threadIdx.x;
    if (e < E) atomicAdd(&g_cnt[col[e]], 1);
}

// ---------------- scan (+ dinv/sdeg/cursor fused) ----------------
__global__ __launch_bounds__(1024) void scan1_kernel() {
    __shared__ int sh[1024];
    int i = blockIdx.x * 1024 + threadIdx.x;
    int v = (i < NN) ? g_cnt[i] : 0;
    sh[threadIdx.x] = v;
    __syncthreads();
#pragma unroll
    for (int off = 1; off < 1024; off <<= 1) {
        int t = 0;
        if (threadIdx.x >= off) t = sh[threadIdx.x - off];
        __syncthreads();
        if (threadIdx.x >= off) sh[threadIdx.x] += t;
        __syncthreads();
    }
    if (i < NN) {
        g_off[i] = sh[threadIdx.x] - v;
        float deg = (float)(v + 1);          // + self loop
        g_dinv[i] = rsqrtf(deg);
        g_sdeg[i] = sqrtf(deg);
        g_cursor[i] = 0;
    }
    if (threadIdx.x == 1023) g_bsum[blockIdx.x] = sh[1023];
}

// warp-scan over the ~98 block sums
__global__ void scan2_kernel() {
    int lane = threadIdx.x;
    int run = 0;
    for (int b0 = 0; b0 < NB_SCAN; b0 += 32) {
        int idx = b0 + lane;
        int orig = (idx < NB_SCAN) ? g_bsum[idx] : 0;
        int v = orig;
#pragma unroll
        for (int off = 1; off < 32; off <<= 1) {
            int t = __shfl_up_sync(0xFFFFFFFFu, v, off);
            if (lane >= off) v += t;
        }
        if (idx < NB_SCAN) g_bsum[idx] = run + v - orig;  // exclusive
        run += __shfl_sync(0xFFFFFFFFu, v, 31);
    }
    if (lane == 0) g_off[NN] = run;
}

__global__ __launch_bounds__(1024) void scan3_kernel() {
    int i = blockIdx.x * 1024 + threadIdx.x;
    if (i < NN) g_off[i] += g_bsum[blockIdx.x];
}

// ---------------- CSR fill (+ sentinel rows in history slices) ----------------
__global__ void fill_kernel(const int* __restrict__ row, const int* __restrict__ col, int E) {
    int e = blockIdx.x * blockDim.x + threadIdx.x;
    if (e < (KH + 1) * 32) {   // zero the sentinel row (index NN) in every slice
        int k = e >> 5, l = e & 31;
        g_yH[(size_t)k * SLICE + (size_t)NN * 32 + l] = __float2half2_rn(0.0f);
    }
    if (e < E) {
        int c = col[e];
        int p = atomicAdd(&g_cursor[c], 1);
        g_src[g_off[c] + p] = row[e];
    }
}

// ---------------- tensor-core MLP (R9 best: 256 threads / 128 rows) ----------------
// y0 = dinv * (relu(x@W1+b1)@W2 + b2) -> g_yH slice 0 (fp16)
__global__ __launch_bounds__(256) void mlp_kernel(
    const float* __restrict__ x,
    const float* __restrict__ W1, const float* __restrict__ b1,
    const float* __restrict__ W2, const float* __restrict__ b2)
{
    __shared__ __half Ax[128][72];   // x tile (then h1 tile), padded pitch
    __shared__ __half Wt[64][72];    // W chunk transposed: Wt[n][k]

    const int t = threadIdx.x;
    const int lane = t & 31;
    const int w = t >> 5;
    const int row0 = blockIdx.x * 128;
    const int wr0 = w * 16;

    const int frow = lane >> 2;       // 0..7
    const int fkp  = (lane & 3) * 2;  // 0,2,4,6

    float c[8][4];
#pragma unroll
    for (int nt = 0; nt < 8; nt++)
#pragma unroll
        for (int i = 0; i < 4; i++) c[nt][i] = 0.0f;

    for (int s = 0; s < 8; s++) {
        const int k0 = s * 64;
        __syncthreads();
        // ---- stage x[rows, k0:k0+64] -> Ax (fp16), zero-pad beyond FD ----
        {
            int c4 = lane & 15;
            int hh = lane >> 4;
#pragma unroll
            for (int rr = 0; rr < 8; rr++) {
                int rl = rr * 2 + hh;
                int gr = row0 + wr0 + rl;
                int gk = k0 + c4 * 4;
                float4 xv = make_float4(0.f, 0.f, 0.f, 0.f);
                if (gr < NN && gk < FD)
                    xv = *reinterpret_cast<const float4*>(&x[(size_t)gr * FD + gk]);
                __half2 p0 = __floats2half2_rn(xv.x, xv.y);
                __half2 p1 = __floats2half2_rn(xv.z, xv.w);
                uint2 pk;
                pk.x = *reinterpret_cast<unsigned*>(&p0);
                pk.y = *reinterpret_cast<unsigned*>(&p1);
                *reinterpret_cast<uint2*>(&Ax[wr0 + rl][c4 * 4]) = pk;
            }
        }
        // ---- stage W1[k0:k0+64, :] transposed -> Wt[n][k] ----
        {
            int n = t & 63;
            int kb = t >> 6;
#pragma unroll
            for (int i = 0; i < 16; i++) {
                int kk = kb + i * 4;
                int gk = k0 + kk;
                Wt[n][kk] = (gk < FD) ? __float2half(W1[gk * 64 + n]) : __half(0.0f);
            }
        }
        __syncthreads();
#pragma unroll
        for (int ks = 0; ks < 4; ks++) {
            const int kb = ks * 16;
            unsigned a0 = *reinterpret_cast<const unsigned*>(&Ax[wr0 + frow][kb + fkp]);
            unsigned a1 = *reinterpret_cast<const unsigned*>(&Ax[wr0 + frow + 8][kb + fkp]);
            unsigned a2 = *reinterpret_cast<const unsigned*>(&Ax[wr0 + frow][kb + fkp + 8]);
            unsigned a3 = *reinterpret_cast<const unsigned*>(&Ax[wr0 + frow + 8][kb + fkp + 8]);
#pragma unroll
            for (int nt = 0; nt < 8; nt++) {
                int n = nt * 8 + frow;
                unsigned b0 = *reinterpret_cast<const unsigned*>(&Wt[n][kb + fkp]);
                unsigned b1r = *reinterpret_cast<const unsigned*>(&Wt[n][kb + fkp + 8]);
                asm volatile(
                    "mma.sync.aligned.m16n8k16.row.col.f32.f16.f16.f32 "
                    "{%0,%1,%2,%3}, {%4,%5,%6,%7}, {%8,%9}, {%0,%1,%2,%3};"
                    : "+f"(c[nt][0]), "+f"(c[nt][1]), "+f"(c[nt][2]), "+f"(c[nt][3])
                    : "r"(a0), "r"(a1), "r"(a2), "r"(a3), "r"(b0), "r"(b1r));
            }
        }
    }

    // ---- epilogue 1: h1 = relu(c + b1) -> Ax ----
#pragma unroll
    for (int nt = 0; nt < 8; nt++) {
        int n0 = nt * 8 + fkp;
        float2 bb = __ldg(reinterpret_cast<const float2*>(&b1[n0]));
        float h00 = fmaxf(c[nt][0] + bb.x, 0.f);
        float h01 = fmaxf(c[nt][1] + bb.y, 0.f);
        float h10 = fmaxf(c[nt][2] + bb.x, 0.f);
        float h11 = fmaxf(c[nt][3] + bb.y, 0.f);
        __half2 p0 = __floats2half2_rn(h00, h01);
        __half2 p1 = __floats2half2_rn(h10, h11);
        *reinterpret_cast<unsigned*>(&Ax[wr0 + frow][n0]) = *reinterpret_cast<unsigned*>(&p0);
        *reinterpret_cast<unsigned*>(&Ax[wr0 + frow + 8][n0]) = *reinterpret_cast<unsigned*>(&p1);
    }
    __syncthreads();
    // ---- stage W2 transposed -> Wt ----
    {
        int n = t & 63;
        int kb = t >> 6;
#pragma unroll
        for (int i = 0; i < 16; i++) {
            int kk = kb + i * 4;
            Wt[n][kk] = __float2half(W2[kk * 64 + n]);
        }
    }
#pragma unroll
    for (int nt = 0; nt < 8; nt++)
#pragma unroll
        for (int i = 0; i < 4; i++) c[nt][i] = 0.0f;
    __syncthreads();

    // ---- GEMM2: h1 @ W2 ----
#pragma unroll
    for (int ks = 0; ks < 4; ks++) {
        const int kb = ks * 16;
        unsigned a0 = *reinterpret_cast<const unsigned*>(&Ax[wr0 + frow][kb + fkp]);
        unsigned a1 = *reinterpret_cast<const unsigned*>(&Ax[wr0 + frow + 8][kb + fkp]);
        unsigned a2 = *reinterpret_cast<const unsigned*>(&Ax[wr0 + frow][kb + fkp + 8]);
        unsigned a3 = *reinterpret_cast<const unsigned*>(&Ax[wr0 + frow + 8][kb + fkp + 8]);
#pragma unroll
        for (int nt = 0; nt < 8; nt++) {
            int n = nt * 8 + frow;
            unsigned b0 = *reinterpret_cast<const unsigned*>(&Wt[n][kb + fkp]);
            unsigned b1r = *reinterpret_cast<const unsigned*>(&Wt[n][kb + fkp + 8]);
            asm volatile(
                "mma.sync.aligned.m16n8k16.row.col.f32.f16.f16.f32 "
                "{%0,%1,%2,%3}, {%4,%5,%6,%7}, {%8,%9}, {%0,%1,%2,%3};"
                : "+f"(c[nt][0]), "+f"(c[nt][1]), "+f"(c[nt][2]), "+f"(c[nt][3])
                : "r"(a0), "r"(a1), "r"(a2), "r"(a3), "r"(b0), "r"(b1r));
        }
    }

    // ---- epilogue 2: y0 = dinv*(c+b2) -> g_yH slice 0 ----
    int gr0 = row0 + wr0 + frow;
    int gr1 = gr0 + 8;
    float d0 = (gr0 < NN) ? g_dinv[gr0] : 0.f;
    float d1 = (gr1 < NN) ? g_dinv[gr1] : 0.f;
#pragma unroll
    for (int nt = 0; nt < 8; nt++) {
        int n0 = nt * 8 + fkp;
        float2 bb = __ldg(reinterpret_cast<const float2*>(&b2[n0]));
        float y00 = d0 * (c[nt][0] + bb.x);
        float y01 = d0 * (c[nt][1] + bb.y);
        float y10 = d1 * (c[nt][2] + bb.x);
        float y11 = d1 * (c[nt][3] + bb.y);
        if (gr0 < NN) g_yH[(size_t)gr0 * 32 + n0 / 2] = __floats2half2_rn(y00, y01);
        if (gr1 < NN) g_yH[(size_t)gr1 * 32 + n0 / 2] = __floats2half2_rn(y10, y11);
    }
}

// ---------------- gather core shared by both propagate kernels ----------------
__device__ __forceinline__ void gather_sum(const __half2* __restrict__ y,
                                           int node, int lane,
                                           float& ax, float& ay) {
    float2 self = __half22float2(__ldg(&y[(size_t)node * 32 + lane]));
    ax = self.x; ay = self.y;   // self-loop term

    int beg = g_off[node];
    int end = g_off[node + 1];
    int nfull = (end - beg) & ~31;
    int i = beg;

    // ---- full 32-edge blocks: no guards inside ----
    for (; i < beg + nfull; i += 32) {
        int s = __ldg(&g_src[i + lane]);
#pragma unroll
        for (int t = 0; t < 4; t++) {
            __half2 h0 = __float2half2_rn(0.0f);
            __half2 h1 = __float2half2_rn(0.0f);
#pragma unroll
            for (int j = 0; j < 4; j++) {
                int sj0 = __shfl_sync(0xFFFFFFFFu, s, t * 8 + j);
                int sj1 = __shfl_sync(0xFFFFFFFFu, s, t * 8 + 4 + j);
                h0 = __hadd2(h0, __ldg(&y[(size_t)sj0 * 32 + lane]));
                h1 = __hadd2(h1, __ldg(&y[(size_t)sj1 * 32 + lane]));
            }
            float2 f = __half22float2(__hadd2(h0, h1));
            ax += f.x;
            ay += f.y;
        }
    }

    // ---- tail (< 32 edges): guarded per 8-chunk ----
    if (i < end) {
        int s = (i + lane < end) ? __ldg(&g_src[i + lane]) : NN;  // sentinel zero row
#pragma unroll
        for (int t = 0; t < 4; t++) {
            if (i + t * 8 < end) {
                __half2 h0 = __float2half2_rn(0.0f);
                __half2 h1 = __float2half2_rn(0.0f);
#pragma unroll
                for (int j = 0; j < 4; j++) {
                    int sj0 = __shfl_sync(0xFFFFFFFFu, s, t * 8 + j);
                    int sj1 = __shfl_sync(0xFFFFFFFFu, s, t * 8 + 4 + j);
                    h0 = __hadd2(h0, __ldg(&y[(size_t)sj0 * 32 + lane]));
                    h1 = __hadd2(h1, __ldg(&y[(size_t)sj1 * 32 + lane]));
                }
                float2 f = __half22float2(__hadd2(h0, h1));
                ax += f.x;
                ay += f.y;
            }
        }
    }
}

// ---------------- pull propagation hops 0..KH-2 ----------------
__global__ __launch_bounds__(256) void propagate_kernel(int k) {
    const __half2* __restrict__ y = g_yH + (size_t)k * SLICE;
    __half2* __restrict__ yn = g_yH + (size_t)(k + 1) * SLICE;
    int node = (blockIdx.x * blockDim.x + threadIdx.x) >> 5;
    int lane = threadIdx.x & 31;
    if (node >= NN) return;

    float ax, ay;
    gather_sum(y, node, lane, ax, ay);

    float d = g_dinv[node];
    float d2 = d * d;
    yn[(size_t)node * 32 + lane] = __floats2half2_rn(d2 * ax, d2 * ay);
}

// ---------------- last hop fused with PPR sum + log_softmax ----------------
__global__ __launch_bounds__(256) void propagate_final_kernel(
    const float* __restrict__ temp, float* __restrict__ out)
{
    const __half2* __restrict__ y = g_yH + (size_t)(KH - 1) * SLICE;
    int node = (blockIdx.x * blockDim.x + threadIdx.x) >> 5;
    int lane = threadIdx.x & 31;
    if (node >= NN) return;

    float ax, ay;
    gather_sum(y, node, lane, ax, ay);

    float d = g_dinv[node];
    float d2 = d * d;
    float tK = __ldg(&temp[KH]);
    float hx = tK * d2 * ax;           // y_K contribution, fp32 (never rounded)
    float hy = tK * d2 * ay;

#pragma unroll
    for (int k = 0; k < KH; k++) {
        float tk = __ldg(&temp[k]);
        float2 v = __half22float2(__ldg(&g_yH[(size_t)k * SLICE + (size_t)node * 32 + lane]));
        hx += tk * v.x;
        hy += tk * v.y;
    }

    float sd = g_sdeg[node];
    float a = hx * sd, b = hy * sd;    // features 2*lane, 2*lane+1
    float mx = fmaxf(a, b);
#pragma unroll
    for (int off = 16; off > 0; off >>= 1)
        mx = fmaxf(mx, __shfl_xor_sync(0xFFFFFFFFu, mx, off));
    float s = expf(a - mx) + expf(b - mx);
#pragma unroll
    for (int off = 16; off > 0; off >>= 1)
        s += __shfl_xor_sync(0xFFFFFFFFu, s, off);
    float l = mx + logf(s);
    *reinterpret_cast<float2*>(&out[(size_t)node * NC + lane * 2]) = make_float2(a - l, b - l);
}

// ---------------- launch ----------------
extern "C" void kernel_launch(void* const* d_in, const int* in_sizes, int n_in,
                              void* d_out, int out_size)
{
    const float* x    = (const float*)d_in[0];
    const int*   ei   = (const int*)d_in[1];
    const float* W1   = (const float*)d_in[2];
    const float* b1   = (const float*)d_in[3];
    const float* W2   = (const float*)d_in[4];
    const float* b2   = (const float*)d_in[5];
    const float* temp = (const float*)d_in[6];
    float* out = (float*)d_out;

    const int E = in_sizes[1] / 2;
    const int* row = ei;       // source
    const int* col = ei + E;   // target

    // CSR build (dinv fused into scan1)
    cnt_zero_kernel<<<(NN + 255) / 256, 256>>>();
    cnt_acc_kernel<<<(E + 255) / 256, 256>>>(col, E);
    scan1_kernel<<<NB_SCAN, 1024>>>();
    scan2_kernel<<<1, 32>>>();
    scan3_kernel<<<NB_SCAN, 1024>>>();
    fill_kernel<<<(E + 255) / 256, 256>>>(row, col, E);

    // MLP -> y0 in g_yH slice 0 (needs g_dinv from scan1)
    mlp_kernel<<<(NN + 127) / 128, 256>>>(x, W1, b1, W2, b2);

    // pull propagation: 1 warp per node; last hop fused with output
    int pblocks = (NN * 32 + 255) / 256;
    for (int k = 0; k < KH - 1; k++) {
        propagate_kernel<<<pblocks, 256>>>(k);
    }
    propagate_final_kernel<<<pblocks, 256>>>(temp, out);
}

// round 13
// speedup vs baseline: 1.1383x; 1.0553x over previous
#include <cuda_runtime.h>
#include <cuda_fp16.h>
#include <math.h>

#define NN 100000
#define FD 500
#define NC 64
#define KH 10
#define EMAX 3200000
#define NB_SCAN ((NN + 1023) / 1024)
#define SLICE ((size_t)(NN + 1) * 32)   // half2 per y slice (+1 sentinel row)

// ---- scratch (no allocations allowed) ----
__device__ __half2 g_yH[(size_t)(KH + 1) * SLICE]; // y_0..y_K history (fp16)
__device__ float g_dinv[NN];
__device__ float g_sdeg[NN];
__device__ int   g_cnt[NN];
__device__ int   g_cursor[NN];
__device__ int   g_off[NN + 1];
__device__ int   g_bsum[NB_SCAN];
__device__ int   g_src[EMAX];

// ---------------- in-degree count ----------------
__global__ void cnt_zero_kernel() {
    int i = blockIdx.x * blockDim.x + threadIdx.x;
    if (i < NN) g_cnt[i] = 0;
}

__global__ void cnt_acc_kernel(const int* __restrict__ col, int E) {
    int e = blockIdx.x * blockDim.x + threadIdx.x;
    if (e < E) atomicAdd(&g_cnt[col[e]], 1);
}

// ---------------- scan (+ dinv/sdeg/cursor fused) ----------------
__global__ __launch_bounds__(1024) void scan1_kernel() {
    __shared__ int sh[1024];
    int i = blockIdx.x * 1024 + threadIdx.x;
    int v = (i < NN) ? g_cnt[i] : 0;
    sh[threadIdx.x] = v;
    __syncthreads();
#pragma unroll
    for (int off = 1; off < 1024; off <<= 1) {
        int t = 0;
        if (threadIdx.x >= off) t = sh[threadIdx.x - off];
        __syncthreads();
        if (threadIdx.x >= off) sh[threadIdx.x] += t;
        __syncthreads();
    }
    if (i < NN) {
        g_off[i] = sh[threadIdx.x] - v;
        float deg = (float)(v + 1);          // + self loop
        g_dinv[i] = rsqrtf(deg);
        g_sdeg[i] = sqrtf(deg);
        g_cursor[i] = 0;
    }
    if (threadIdx.x == 1023) g_bsum[blockIdx.x] = sh[1023];
}

// warp-scan over the ~98 block sums
__global__ void scan2_kernel() {
    int lane = threadIdx.x;
    int run = 0;
    for (int b0 = 0; b0 < NB_SCAN; b0 += 32) {
        int idx = b0 + lane;
        int orig = (idx < NB_SCAN) ? g_bsum[idx] : 0;
        int v = orig;
#pragma unroll
        for (int off = 1; off < 32; off <<= 1) {
            int t = __shfl_up_sync(0xFFFFFFFFu, v, off);
            if (lane >= off) v += t;
        }
        if (idx < NB_SCAN) g_bsum[idx] = run + v - orig;  // exclusive
        run += __shfl_sync(0xFFFFFFFFu, v, 31);
    }
    if (lane == 0) g_off[NN] = run;
}

__global__ __launch_bounds__(1024) void scan3_kernel() {
    int i = blockIdx.x * 1024 + threadIdx.x;
    if (i < NN) g_off[i] += g_bsum[blockIdx.x];
}

// ---------------- CSR fill (+ sentinel rows in history slices) ----------------
__global__ void fill_kernel(const int* __restrict__ row, const int* __restrict__ col, int E) {
    int e = blockIdx.x * blockDim.x + threadIdx.x;
    if (e < (KH + 1) * 32) {   // zero the sentinel row (index NN) in every slice
        int k = e >> 5, l = e & 31;
        g_yH[(size_t)k * SLICE + (size_t)NN * 32 + l] = __float2half2_rn(0.0f);
    }
    if (e < E) {
        int c = col[e];
        int p = atomicAdd(&g_cursor[c], 1);
        g_src[g_off[c] + p] = row[e];
    }
}

// ---------------- tensor-core MLP (R9 shape; NO dinv dependency) ----------------
// h = relu(x@W1+b1)@W2 + b2 -> g_yH slice 0 (fp16, unscaled)
__global__ __launch_bounds__(256) void mlp_kernel(
    const float* __restrict__ x,
    const float* __restrict__ W1, const float* __restrict__ b1,
    const float* __restrict__ W2, const float* __restrict__ b2)
{
    __shared__ __half Ax[128][72];   // x tile (then h1 tile), padded pitch
    __shared__ __half Wt[64][72];    // W chunk transposed: Wt[n][k]

    const int t = threadIdx.x;
    const int lane = t & 31;
    const int w = t >> 5;
    const int row0 = blockIdx.x * 128;
    const int wr0 = w * 16;

    const int frow = lane >> 2;       // 0..7
    const int fkp  = (lane & 3) * 2;  // 0,2,4,6

    float c[8][4];
#pragma unroll
    for (int nt = 0; nt < 8; nt++)
#pragma unroll
        for (int i = 0; i < 4; i++) c[nt][i] = 0.0f;

    for (int s = 0; s < 8; s++) {
        const int k0 = s * 64;
        __syncthreads();
        // ---- stage x[rows, k0:k0+64] -> Ax (fp16), zero-pad beyond FD ----
        {
            int c4 = lane & 15;
            int hh = lane >> 4;
#pragma unroll
            for (int rr = 0; rr < 8; rr++) {
                int rl = rr * 2 + hh;
                int gr = row0 + wr0 + rl;
                int gk = k0 + c4 * 4;
                float4 xv = make_float4(0.f, 0.f, 0.f, 0.f);
                if (gr < NN && gk < FD)
                    xv = *reinterpret_cast<const float4*>(&x[(size_t)gr * FD + gk]);
                __half2 p0 = __floats2half2_rn(xv.x, xv.y);
                __half2 p1 = __floats2half2_rn(xv.z, xv.w);
                uint2 pk;
                pk.x = *reinterpret_cast<unsigned*>(&p0);
                pk.y = *reinterpret_cast<unsigned*>(&p1);
                *reinterpret_cast<uint2*>(&Ax[wr0 + rl][c4 * 4]) = pk;
            }
        }
        // ---- stage W1[k0:k0+64, :] transposed -> Wt[n][k] ----
        {
            int n = t & 63;
            int kb = t >> 6;
#pragma unroll
            for (int i = 0; i < 16; i++) {
                int kk = kb + i * 4;
                int gk = k0 + kk;
                Wt[n][kk] = (gk < FD) ? __float2half(W1[gk * 64 + n]) : __half(0.0f);
            }
        }
        __syncthreads();
#pragma unroll
        for (int ks = 0; ks < 4; ks++) {
            const int kb = ks * 16;
            unsigned a0 = *reinterpret_cast<const unsigned*>(&Ax[wr0 + frow][kb + fkp]);
            unsigned a1 = *reinterpret_cast<const unsigned*>(&Ax[wr0 + frow + 8][kb + fkp]);
            unsigned a2 = *reinterpret_cast<const unsigned*>(&Ax[wr0 + frow][kb + fkp + 8]);
            unsigned a3 = *reinterpret_cast<const unsigned*>(&Ax[wr0 + frow + 8][kb + fkp + 8]);
#pragma unroll
            for (int nt = 0; nt < 8; nt++) {
                int n = nt * 8 + frow;
                unsigned b0 = *reinterpret_cast<const unsigned*>(&Wt[n][kb + fkp]);
                unsigned b1r = *reinterpret_cast<const unsigned*>(&Wt[n][kb + fkp + 8]);
                asm volatile(
                    "mma.sync.aligned.m16n8k16.row.col.f32.f16.f16.f32 "
                    "{%0,%1,%2,%3}, {%4,%5,%6,%7}, {%8,%9}, {%0,%1,%2,%3};"
                    : "+f"(c[nt][0]), "+f"(c[nt][1]), "+f"(c[nt][2]), "+f"(c[nt][3])
                    : "r"(a0), "r"(a1), "r"(a2), "r"(a3), "r"(b0), "r"(b1r));
            }
        }
    }

    // ---- epilogue 1: h1 = relu(c + b1) -> Ax ----
#pragma unroll
    for (int nt = 0; nt < 8; nt++) {
        int n0 = nt * 8 + fkp;
        float2 bb = __ldg(reinterpret_cast<const float2*>(&b1[n0]));
        float h00 = fmaxf(c[nt][0] + bb.x, 0.f);
        float h01 = fmaxf(c[nt][1] + bb.y, 0.f);
        float h10 = fmaxf(c[nt][2] + bb.x, 0.f);
        float h11 = fmaxf(c[nt][3] + bb.y, 0.f);
        __half2 p0 = __floats2half2_rn(h00, h01);
        __half2 p1 = __floats2half2_rn(h10, h11);
        *reinterpret_cast<unsigned*>(&Ax[wr0 + frow][n0]) = *reinterpret_cast<unsigned*>(&p0);
        *reinterpret_cast<unsigned*>(&Ax[wr0 + frow + 8][n0]) = *reinterpret_cast<unsigned*>(&p1);
    }
    __syncthreads();
    // ---- stage W2 transposed -> Wt ----
    {
        int n = t & 63;
        int kb = t >> 6;
#pragma unroll
        for (int i = 0; i < 16; i++) {
            int kk = kb + i * 4;
            Wt[n][kk] = __float2half(W2[kk * 64 + n]);
        }
    }
#pragma unroll
    for (int nt = 0; nt < 8; nt++)
#pragma unroll
        for (int i = 0; i < 4; i++) c[nt][i] = 0.0f;
    __syncthreads();

    // ---- GEMM2: h1 @ W2 ----
#pragma unroll
    for (int ks = 0; ks < 4; ks++) {
        const int kb = ks * 16;
        unsigned a0 = *reinterpret_cast<const unsigned*>(&Ax[wr0 + frow][kb + fkp]);
        unsigned a1 = *reinterpret_cast<const unsigned*>(&Ax[wr0 + frow + 8][kb + fkp]);
        unsigned a2 = *reinterpret_cast<const unsigned*>(&Ax[wr0 + frow][kb + fkp + 8]);
        unsigned a3 = *reinterpret_cast<const unsigned*>(&Ax[wr0 + frow + 8][kb + fkp + 8]);
#pragma unroll
        for (int nt = 0; nt < 8; nt++) {
            int n = nt * 8 + frow;
            unsigned b0 = *reinterpret_cast<const unsigned*>(&Wt[n][kb + fkp]);
            unsigned b1r = *reinterpret_cast<const unsigned*>(&Wt[n][kb + fkp + 8]);
            asm volatile(
                "mma.sync.aligned.m16n8k16.row.col.f32.f16.f16.f32 "
                "{%0,%1,%2,%3}, {%4,%5,%6,%7}, {%8,%9}, {%0,%1,%2,%3};"
                : "+f"(c[nt][0]), "+f"(c[nt][1]), "+f"(c[nt][2]), "+f"(c[nt][3])
                : "r"(a0), "r"(a1), "r"(a2), "r"(a3), "r"(b0), "r"(b1r));
        }
    }

    // ---- epilogue 2: h (+b2, unscaled) -> g_yH slice 0 ----
    int gr0 = row0 + wr0 + frow;
    int gr1 = gr0 + 8;
#pragma unroll
    for (int nt = 0; nt < 8; nt++) {
        int n0 = nt * 8 + fkp;
        float2 bb = __ldg(reinterpret_cast<const float2*>(&b2[n0]));
        float y00 = c[nt][0] + bb.x;
        float y01 = c[nt][1] + bb.y;
        float y10 = c[nt][2] + bb.x;
        float y11 = c[nt][3] + bb.y;
        if (gr0 < NN) g_yH[(size_t)gr0 * 32 + n0 / 2] = __floats2half2_rn(y00, y01);
        if (gr1 < NN) g_yH[(size_t)gr1 * 32 + n0 / 2] = __floats2half2_rn(y10, y11);
    }
}

// ---------------- y0 *= dinv (after join) ----------------
__global__ void scale0_kernel() {
    int idx = blockIdx.x * blockDim.x + threadIdx.x;   // over NN*8 uint4
    if (idx >= NN * 8) return;
    int node = idx >> 3;
    float d = g_dinv[node];
    uint4* p = reinterpret_cast<uint4*>(g_yH) + idx;
    uint4 v = *p;
    __half2 h[4];
    *reinterpret_cast<uint4*>(h) = v;
#pragma unroll
    for (int t = 0; t < 4; t++) {
        float2 f = __half22float2(h[t]);
        h[t] = __floats2half2_rn(d * f.x, d * f.y);
    }
    *p = *reinterpret_cast<uint4*>(h);
}

// ---------------- pull propagation (R9 best, verbatim) ----------------
__global__ __launch_bounds__(256) void propagate_kernel(int k) {
    const __half2* __restrict__ y = g_yH + (size_t)k * SLICE;
    __half2* __restrict__ yn = g_yH + (size_t)(k + 1) * SLICE;
    int node = (blockIdx.x * blockDim.x + threadIdx.x) >> 5;
    int lane = threadIdx.x & 31;
    if (node >= NN) return;

    float d = g_dinv[node];
    float2 self = __half22float2(__ldg(&y[(size_t)node * 32 + lane]));
    float ax = self.x, ay = self.y;   // self-loop term

    int beg = g_off[node];
    int end = g_off[node + 1];
    int nfull = (end - beg) & ~31;
    int i = beg;

    for (; i < beg + nfull; i += 32) {
        int s = __ldg(&g_src[i + lane]);
#pragma unroll
        for (int t = 0; t < 4; t++) {
            __half2 h0 = __float2half2_rn(0.0f);
            __half2 h1 = __float2half2_rn(0.0f);
#pragma unroll
            for (int j = 0; j < 4; j++) {
                int sj0 = __shfl_sync(0xFFFFFFFFu, s, t * 8 + j);
                int sj1 = __shfl_sync(0xFFFFFFFFu, s, t * 8 + 4 + j);
                h0 = __hadd2(h0, __ldg(&y[(size_t)sj0 * 32 + lane]));
                h1 = __hadd2(h1, __ldg(&y[(size_t)sj1 * 32 + lane]));
            }
            float2 f = __half22float2(__hadd2(h0, h1));
            ax += f.x;
            ay += f.y;
        }
    }

    if (i < end) {
        int s = (i + lane < end) ? __ldg(&g_src[i + lane]) : NN;  // sentinel zero row
#pragma unroll
        for (int t = 0; t < 4; t++) {
            if (i + t * 8 < end) {
                __half2 h0 = __float2half2_rn(0.0f);
                __half2 h1 = __float2half2_rn(0.0f);
#pragma unroll
                for (int j = 0; j < 4; j++) {
                    int sj0 = __shfl_sync(0xFFFFFFFFu, s, t * 8 + j);
                    int sj1 = __shfl_sync(0xFFFFFFFFu, s, t * 8 + 4 + j);
                    h0 = __hadd2(h0, __ldg(&y[(size_t)sj0 * 32 + lane]));
                    h1 = __hadd2(h1, __ldg(&y[(size_t)sj1 * 32 + lane]));
                }
                float2 f = __half22float2(__hadd2(h0, h1));
                ax += f.x;
                ay += f.y;
            }
        }
    }

    float d2 = d * d;
    yn[(size_t)node * 32 + lane] = __floats2half2_rn(d2 * ax, d2 * ay);
}

// ---------------- final: hidden = sdeg * sum_k temp[k]*y_k ; log_softmax ----------------
__global__ void final_kernel(const float* __restrict__ temp, float* __restrict__ out) {
    int node = (blockIdx.x * blockDim.x + threadIdx.x) >> 5;
    int lane = threadIdx.x & 31;
    if (node >= NN) return;
    float sd = g_sdeg[node];
    float ax = 0.f, ay = 0.f;
#pragma unroll
    for (int k = 0; k <= KH; k++) {
        float tk = __ldg(&temp[k]);
        float2 v = __half22float2(__ldg(&g_yH[(size_t)k * SLICE + (size_t)node * 32 + lane]));
        ax += tk * v.x;
        ay += tk * v.y;
    }
    float a = ax * sd, b = ay * sd;   // features 2*lane, 2*lane+1
    float mx = fmaxf(a, b);
#pragma unroll
    for (int off = 16; off > 0; off >>= 1)
        mx = fmaxf(mx, __shfl_xor_sync(0xFFFFFFFFu, mx, off));
    float s = expf(a - mx) + expf(b - mx);
#pragma unroll
    for (int off = 16; off > 0; off >>= 1)
        s += __shfl_xor_sync(0xFFFFFFFFu, s, off);
    float l = mx + logf(s);
    *reinterpret_cast<float2*>(&out[(size_t)node * NC + lane * 2]) = make_float2(a - l, b - l);
}

// ---------------- launch ----------------
extern "C" void kernel_launch(void* const* d_in, const int* in_sizes, int n_in,
                              void* d_out, int out_size)
{
    const float* x    = (const float*)d_in[0];
    const int*   ei   = (const int*)d_in[1];
    const float* W1   = (const float*)d_in[2];
    const float* b1   = (const float*)d_in[3];
    const float* W2   = (const float*)d_in[4];
    const float* b2   = (const float*)d_in[5];
    const float* temp = (const float*)d_in[6];
    float* out = (float*)d_out;

    const int E = in_sizes[1] / 2;
    const int* row = ei;       // source
    const int* col = ei + E;   // target

    // Try to fork MLP onto a side stream (graph-capturable fork/join pattern).
    cudaStream_t s1 = 0;
    cudaEvent_t evA = 0, evB = 0;
    bool forked =
        (cudaStreamCreateWithFlags(&s1, cudaStreamNonBlocking) == cudaSuccess) &&
        (cudaEventCreateWithFlags(&evA, cudaEventDisableTiming) == cudaSuccess) &&
        (cudaEventCreateWithFlags(&evB, cudaEventDisableTiming) == cudaSuccess);

    if (forked) {
        // fork: side stream runs the (dependency-free) MLP
        cudaEventRecord(evA, (cudaStream_t)0);
        cudaStreamWaitEvent(s1, evA, 0);
        mlp_kernel<<<(NN + 127) / 128, 256, 0, s1>>>(x, W1, b1, W2, b2);
        cudaEventRecord(evB, s1);
    } else {
        mlp_kernel<<<(NN + 127) / 128, 256>>>(x, W1, b1, W2, b2);
    }

    // capture stream: CSR build (independent of MLP)
    cnt_zero_kernel<<<(NN + 255) / 256, 256>>>();
    cnt_acc_kernel<<<(E + 255) / 256, 256>>>(col, E);
    scan1_kernel<<<NB_SCAN, 1024>>>();
    scan2_kernel<<<1, 32>>>();
    scan3_kernel<<<NB_SCAN, 1024>>>();
    fill_kernel<<<(E + 255) / 256, 256>>>(row, col, E);

    if (forked) {
        cudaStreamWaitEvent((cudaStream_t)0, evB, 0);   // join
    }

    // y0 = dinv * h
    scale0_kernel<<<(NN * 8 + 255) / 256, 256>>>();

    // pull propagation: 1 warp per node
    int pblocks = (NN * 32 + 255) / 256;
    for (int k = 0; k < KH; k++) {
        propagate_kernel<<<pblocks, 256>>>(k);
    }

    final_kernel<<<(NN * 32 + 255) / 256, 256>>>(temp, out);
    // NOTE: s1/evA/evB intentionally not destroyed here — destroying objects
    // that participated in an active capture can invalidate it; the few leaked
    // handles (kernel_launch is called O(1) times) are host-side only.
}